// round 6
// baseline (speedup 1.0000x reference)
#include <cuda_runtime.h>
#include <math.h>

#define PI_D 3.14159265358979323846
#define SQH 0.70710678118654752440f

// ---------------- static device scratch ----------------
__device__ float2 g_S[512 * 2 * 128 * 128];   // state [b][f][X][Y]
__device__ float4 g_U0[128 * 128 * 2];        // mux0 unitaries, bitrev-permuted
__device__ float4 g_U1[2 * 2 * 64 * 64 * 2];
__device__ float4 g_U2[2 * 2 * 32 * 32 * 2];
__device__ float2 g_TW[64];                   // exp(-2*pi*i*t/128)
__device__ int    g_NR[128];                  // bitrev-domain negation table
__device__ float  g_part[512 * 2 * 10];       // partial logits per (b, xc1)

__device__ __forceinline__ float2 cmul(float2 a, float2 b) {
    return make_float2(a.x * b.x - a.y * b.y, a.x * b.y + a.y * b.x);
}
__device__ __forceinline__ float2 cmulc(float2 a, float2 b) {  // a * conj(b)
    return make_float2(a.x * b.x + a.y * b.y, a.y * b.x - a.x * b.y);
}
__device__ __forceinline__ float2 f2add(float2 a, float2 b) { return make_float2(a.x + b.x, a.y + b.y); }
__device__ __forceinline__ float2 f2sub(float2 a, float2 b) { return make_float2(a.x - b.x, a.y - b.y); }
__device__ __forceinline__ float2 f2sc(float2 a, float s) { return make_float2(a.x * s, a.y * s); }
__device__ __forceinline__ float2 csq(float2 a) { return make_float2(a.x * a.x - a.y * a.y, 2.f * a.x * a.y); }

// =====================================================================
// FFT passes. element (line, p) at base[(line&(2^LG1-1))*SL1 + (line>>LG1)*SL2 + p*SP]
// FWD: DIF natural->bitrev; INV: DIT bitrev->natural (conj twiddles), scale on LAST.
// =====================================================================

// radix-8 pass: three radix-2 stages {S+2,S+1,S} (FWD) / {S,S+1,S+2} (INV)
template<bool INV, int NTT, int SP, int SL1, int LG1, int SL2, int LG2, int LOGN, int S, bool LAST>
__device__ __forceinline__ void pass8(float2* __restrict__ base,
                                      const float2* __restrict__ tw, float scale) {
    constexpr int L = 1 << (LG1 + LG2);
    constexpr int ITEMS = L << (LOGN - 3);
    constexpr int h = 1 << S;
    for (int u = threadIdx.x; u < ITEMS; u += NTT) {
        const int line = u & (L - 1);
        const int loff = (line & ((1 << LG1) - 1)) * SL1 + (line >> LG1) * SL2;
        const int v = u >> (LG1 + LG2);
        const int t = v & (h - 1);
        const int p = ((v >> S) << (S + 3)) + t;
        float2* e = base + loff + p * SP;
        float2 d0 = e[0],          d1 = e[h * SP],     d2 = e[2 * h * SP], d3 = e[3 * h * SP];
        float2 d4 = e[4 * h * SP], d5 = e[5 * h * SP], d6 = e[6 * h * SP], d7 = e[7 * h * SP];
        const float2 w  = tw[t << (4 - S)];                         // W(t, 8h)
        const float2 w1 = make_float2(SQH * (w.x + w.y), SQH * (w.y - w.x));
        const float2 w2 = make_float2(w.y, -w.x);
        const float2 w3 = make_float2(SQH * (w.y - w.x), -SQH * (w.x + w.y));
        const float2 u2  = csq(w);                                  // W(t, 4h)
        const float2 u2m = make_float2(u2.y, -u2.x);
        const float2 v4  = csq(u2);                                 // W(t, 2h)
        if constexpr (!INV) {
            float2 s0 = f2add(d0, d4), s1 = f2add(d1, d5), s2 = f2add(d2, d6), s3 = f2add(d3, d7);
            float2 t0 = cmul(f2sub(d0, d4), w);
            float2 t1 = cmul(f2sub(d1, d5), w1);
            float2 t2 = cmul(f2sub(d2, d6), w2);
            float2 t3 = cmul(f2sub(d3, d7), w3);
            float2 a0 = f2add(s0, s2), a2 = cmul(f2sub(s0, s2), u2);
            float2 a1 = f2add(s1, s3), a3 = cmul(f2sub(s1, s3), u2m);
            float2 b0 = f2add(t0, t2), b2 = cmul(f2sub(t0, t2), u2);
            float2 b1 = f2add(t1, t3), b3 = cmul(f2sub(t1, t3), u2m);
            e[0]          = f2add(a0, a1);  e[h * SP]     = cmul(f2sub(a0, a1), v4);
            e[2 * h * SP] = f2add(a2, a3);  e[3 * h * SP] = cmul(f2sub(a2, a3), v4);
            e[4 * h * SP] = f2add(b0, b1);  e[5 * h * SP] = cmul(f2sub(b0, b1), v4);
            e[6 * h * SP] = f2add(b2, b3);  e[7 * h * SP] = cmul(f2sub(b2, b3), v4);
        } else {
            float2 q1 = cmulc(d1, v4), q3 = cmulc(d3, v4), q5 = cmulc(d5, v4), q7 = cmulc(d7, v4);
            float2 c0 = f2add(d0, q1), c1 = f2sub(d0, q1);
            float2 c2 = f2add(d2, q3), c3 = f2sub(d2, q3);
            float2 c4 = f2add(d4, q5), c5 = f2sub(d4, q5);
            float2 c6 = f2add(d6, q7), c7 = f2sub(d6, q7);
            float2 r2 = cmulc(c2, u2), r3 = cmulc(c3, u2m), r6 = cmulc(c6, u2), r7 = cmulc(c7, u2m);
            float2 g0 = f2add(c0, r2), g2 = f2sub(c0, r2);
            float2 g1 = f2add(c1, r3), g3 = f2sub(c1, r3);
            float2 g4 = f2add(c4, r6), g6 = f2sub(c4, r6);
            float2 g5 = f2add(c5, r7), g7 = f2sub(c5, r7);
            float2 h4 = cmulc(g4, w), h5 = cmulc(g5, w1), h6 = cmulc(g6, w2), h7 = cmulc(g7, w3);
            float2 o0 = f2add(g0, h4), o4 = f2sub(g0, h4);
            float2 o1 = f2add(g1, h5), o5 = f2sub(g1, h5);
            float2 o2 = f2add(g2, h6), o6 = f2sub(g2, h6);
            float2 o3 = f2add(g3, h7), o7 = f2sub(g3, h7);
            if constexpr (LAST) {
                o0 = f2sc(o0, scale); o1 = f2sc(o1, scale); o2 = f2sc(o2, scale); o3 = f2sc(o3, scale);
                o4 = f2sc(o4, scale); o5 = f2sc(o5, scale); o6 = f2sc(o6, scale); o7 = f2sc(o7, scale);
            }
            e[0]          = o0; e[h * SP]     = o1; e[2 * h * SP] = o2; e[3 * h * SP] = o3;
            e[4 * h * SP] = o4; e[5 * h * SP] = o5; e[6 * h * SP] = o6; e[7 * h * SP] = o7;
        }
    }
    __syncthreads();
}

// radix-4 pass: stages {S+1, S} (FWD) / {S, S+1} (INV)
template<bool INV, int NTT, int SP, int SL1, int LG1, int SL2, int LG2, int LOGN, int S, bool LAST>
__device__ __forceinline__ void pass4(float2* __restrict__ base,
                                      const float2* __restrict__ tw, float scale) {
    constexpr int L = 1 << (LG1 + LG2);
    constexpr int ITEMS = L << (LOGN - 2);
    constexpr int h = 1 << S;
    for (int u = threadIdx.x; u < ITEMS; u += NTT) {
        const int line = u & (L - 1);
        const int loff = (line & ((1 << LG1) - 1)) * SL1 + (line >> LG1) * SL2;
        const int v = u >> (LG1 + LG2);
        const int t = v & (h - 1);
        const int p = ((v >> S) << (S + 2)) + t;
        float2* e = base + loff + p * SP;
        float2 a = e[0], b = e[h * SP], c = e[2 * h * SP], d = e[3 * h * SP];
        const float2 w0 = tw[t << (5 - S)];
        const float2 w1 = make_float2(w0.y, -w0.x);
        const float2 w2 = csq(w0);
        if constexpr (!INV) {
            float2 ac = f2add(a, c), bd = f2add(b, d);
            float2 cP = cmul(f2sub(a, c), w0);
            float2 dP = cmul(f2sub(b, d), w1);
            e[0]          = f2add(ac, bd);
            e[h * SP]     = cmul(f2sub(ac, bd), w2);
            e[2 * h * SP] = f2add(cP, dP);
            e[3 * h * SP] = cmul(f2sub(cP, dP), w2);
        } else {
            float2 bw = cmulc(b, w2), dw = cmulc(d, w2);
            float2 aP = f2add(a, bw), bP = f2sub(a, bw);
            float2 cP = f2add(c, dw), dP = f2sub(c, dw);
            float2 cw = cmulc(cP, w0), dq = cmulc(dP, w1);
            float2 o0 = f2add(aP, cw), o2 = f2sub(aP, cw);
            float2 o1 = f2add(bP, dq), o3 = f2sub(bP, dq);
            if constexpr (LAST) {
                o0 = f2sc(o0, scale); o1 = f2sc(o1, scale);
                o2 = f2sc(o2, scale); o3 = f2sc(o3, scale);
            }
            e[0] = o0; e[h * SP] = o1; e[2 * h * SP] = o2; e[3 * h * SP] = o3;
        }
    }
    __syncthreads();
}

// radix-2 pass: single stage S
template<bool INV, int NTT, int SP, int SL1, int LG1, int SL2, int LG2, int LOGN, int S, bool LAST>
__device__ __forceinline__ void pass2(float2* __restrict__ base,
                                      const float2* __restrict__ tw, float scale) {
    constexpr int L = 1 << (LG1 + LG2);
    constexpr int ITEMS = L << (LOGN - 1);
    constexpr int h = 1 << S;
    for (int u = threadIdx.x; u < ITEMS; u += NTT) {
        const int line = u & (L - 1);
        const int loff = (line & ((1 << LG1) - 1)) * SL1 + (line >> LG1) * SL2;
        const int v = u >> (LG1 + LG2);
        const int t = v & (h - 1);
        const int p = ((v >> S) << (S + 1)) + t;
        float2* e = base + loff + p * SP;
        float2 a = e[0], b = e[h * SP];
        const float2 w = tw[t << (6 - S)];
        if constexpr (!INV) {
            e[0]      = f2add(a, b);
            e[h * SP] = cmul(f2sub(a, b), w);
        } else {
            float2 bw = cmulc(b, w);
            float2 o0 = f2add(a, bw), o1 = f2sub(a, bw);
            if constexpr (LAST) { o0 = f2sc(o0, scale); o1 = f2sc(o1, scale); }
            e[0] = o0; e[h * SP] = o1;
        }
    }
    __syncthreads();
}

// radix-4 schedule (for p1/p2: low-reg, high-occupancy kernels)
template<bool INV, int NTT, int SP, int SL1, int LG1, int SL2, int LG2, int LOGN>
__device__ __forceinline__ void fft_run(float2* __restrict__ base,
                                        const float2* __restrict__ tw, float scale) {
    if constexpr (!INV) {
        if constexpr (LOGN == 7) {
            pass4<false, NTT, SP, SL1, LG1, SL2, LG2, 7, 5, false>(base, tw, 1.f);
            pass4<false, NTT, SP, SL1, LG1, SL2, LG2, 7, 3, false>(base, tw, 1.f);
            pass4<false, NTT, SP, SL1, LG1, SL2, LG2, 7, 1, false>(base, tw, 1.f);
            pass2<false, NTT, SP, SL1, LG1, SL2, LG2, 7, 0, false>(base, tw, 1.f);
        } else if constexpr (LOGN == 6) {
            pass4<false, NTT, SP, SL1, LG1, SL2, LG2, 6, 4, false>(base, tw, 1.f);
            pass4<false, NTT, SP, SL1, LG1, SL2, LG2, 6, 2, false>(base, tw, 1.f);
            pass4<false, NTT, SP, SL1, LG1, SL2, LG2, 6, 0, false>(base, tw, 1.f);
        } else {
            pass4<false, NTT, SP, SL1, LG1, SL2, LG2, 5, 3, false>(base, tw, 1.f);
            pass4<false, NTT, SP, SL1, LG1, SL2, LG2, 5, 1, false>(base, tw, 1.f);
            pass2<false, NTT, SP, SL1, LG1, SL2, LG2, 5, 0, false>(base, tw, 1.f);
        }
    } else {
        if constexpr (LOGN == 7) {
            pass4<true, NTT, SP, SL1, LG1, SL2, LG2, 7, 0, false>(base, tw, 1.f);
            pass4<true, NTT, SP, SL1, LG1, SL2, LG2, 7, 2, false>(base, tw, 1.f);
            pass4<true, NTT, SP, SL1, LG1, SL2, LG2, 7, 4, false>(base, tw, 1.f);
            pass2<true, NTT, SP, SL1, LG1, SL2, LG2, 7, 6, true >(base, tw, scale);
        } else if constexpr (LOGN == 6) {
            pass4<true, NTT, SP, SL1, LG1, SL2, LG2, 6, 0, false>(base, tw, 1.f);
            pass4<true, NTT, SP, SL1, LG1, SL2, LG2, 6, 2, false>(base, tw, 1.f);
            pass4<true, NTT, SP, SL1, LG1, SL2, LG2, 6, 4, true >(base, tw, scale);
        } else {
            pass4<true, NTT, SP, SL1, LG1, SL2, LG2, 5, 0, false>(base, tw, 1.f);
            pass4<true, NTT, SP, SL1, LG1, SL2, LG2, 5, 2, false>(base, tw, 1.f);
            pass2<true, NTT, SP, SL1, LG1, SL2, LG2, 5, 4, true >(base, tw, scale);
        }
    }
}

// radix-8 schedule (for p35: 512 threads, 128-reg budget, L1-byte-bound)
template<bool INV, int NTT, int SP, int SL1, int LG1, int SL2, int LG2, int LOGN>
__device__ __forceinline__ void fft_run8(float2* __restrict__ base,
                                         const float2* __restrict__ tw, float scale) {
    if constexpr (!INV) {
        if constexpr (LOGN == 7) {
            pass8<false, NTT, SP, SL1, LG1, SL2, LG2, 7, 4, false>(base, tw, 1.f);
            pass8<false, NTT, SP, SL1, LG1, SL2, LG2, 7, 1, false>(base, tw, 1.f);
            pass2<false, NTT, SP, SL1, LG1, SL2, LG2, 7, 0, false>(base, tw, 1.f);
        } else if constexpr (LOGN == 6) {
            pass8<false, NTT, SP, SL1, LG1, SL2, LG2, 6, 3, false>(base, tw, 1.f);
            pass8<false, NTT, SP, SL1, LG1, SL2, LG2, 6, 0, false>(base, tw, 1.f);
        } else {
            pass8<false, NTT, SP, SL1, LG1, SL2, LG2, 5, 2, false>(base, tw, 1.f);
            pass4<false, NTT, SP, SL1, LG1, SL2, LG2, 5, 0, false>(base, tw, 1.f);
        }
    } else {
        if constexpr (LOGN == 7) {
            pass8<true, NTT, SP, SL1, LG1, SL2, LG2, 7, 0, false>(base, tw, 1.f);
            pass8<true, NTT, SP, SL1, LG1, SL2, LG2, 7, 3, false>(base, tw, 1.f);
            pass2<true, NTT, SP, SL1, LG1, SL2, LG2, 7, 6, true >(base, tw, scale);
        } else if constexpr (LOGN == 6) {
            pass8<true, NTT, SP, SL1, LG1, SL2, LG2, 6, 0, false>(base, tw, 1.f);
            pass8<true, NTT, SP, SL1, LG1, SL2, LG2, 6, 3, true >(base, tw, scale);
        } else {
            pass8<true, NTT, SP, SL1, LG1, SL2, LG2, 5, 0, false>(base, tw, 1.f);
            pass4<true, NTT, SP, SL1, LG1, SL2, LG2, 5, 3, true >(base, tw, scale);
        }
    }
}

__device__ __forceinline__ void apply_mux(float2& p0, float2& p1, float4 uA, float4 uB) {
    float2 o0, o1;
    o0.x = uA.x * p0.x - uA.y * p0.y + uA.z * p1.x - uA.w * p1.y;
    o0.y = uA.x * p0.y + uA.y * p0.x + uA.z * p1.y + uA.w * p1.x;
    o1.x = uB.x * p0.x - uB.y * p0.y + uB.z * p1.x - uB.w * p1.y;
    o1.y = uB.x * p0.y + uB.y * p0.x + uB.z * p1.y + uB.w * p1.x;
    p0 = o0; p1 = o1;
}

// ---------------- K0: precompute ----------------
__device__ __forceinline__ void writeU(float4* dst, float axf, float ayf, float azf) {
    double ax = axf, ay = ayf, az = azf;
    double r = sqrt(ax * ax + ay * ay + az * az + 1e-20);
    double cr = cos(r), sn = sin(r) / r;
    dst[0] = make_float4((float)cr, (float)(-az * sn), (float)(-ay * sn), (float)(-ax * sn));
    dst[1] = make_float4((float)(ay * sn), (float)(-ax * sn), (float)cr, (float)(az * sn));
}

__global__ void k0(const float* __restrict__ mux0, const float* __restrict__ mux1,
                   const float* __restrict__ mux2) {
    int idx = blockIdx.x * blockDim.x + threadIdx.x;   // 16384 threads
    if (idx < 64) {
        double ang = -2.0 * PI_D * (double)idx / 128.0;
        g_TW[idx] = make_float2((float)cos(ang), (float)sin(ang));
    }
    if (idx < 128) {
        int k = __brev((unsigned)idx) >> 25;
        g_NR[idx] = (int)(__brev((unsigned)((128 - k) & 127)) >> 25);
    }
    {
        int kxb = idx >> 7, kyb = idx & 127;
        int kx = __brev((unsigned)kxb) >> 25, ky = __brev((unsigned)kyb) >> 25;
        const float* c = mux0 + (kx * 128 + ky) * 3;
        writeU(&g_U0[idx * 2], c[0], c[1], c[2]);
    }
    {
        int cx = idx >> 13, cy = (idx >> 12) & 1, kxb = (idx >> 6) & 63, kyb = idx & 63;
        int kx = __brev((unsigned)kxb) >> 26, ky = __brev((unsigned)kyb) >> 26;
        const float* c = mux1 + (((cx * 2 + cy) * 64 + kx) * 64 + ky) * 3;
        writeU(&g_U1[idx * 2], c[0], c[1], c[2]);
    }
    if (idx < 4096) {
        int cx = idx >> 11, cy = (idx >> 10) & 1, kxb = (idx >> 5) & 31, kyb = idx & 31;
        int kx = __brev((unsigned)kxb) >> 27, ky = __brev((unsigned)kyb) >> 27;
        const float* c = mux2 + (((cx * 2 + cy) * 32 + kx) * 32 + ky) * 3;
        writeU(&g_U2[idx * 2], c[0], c[1], c[2]);
    }
}

// ---------------- P1: encode + y-FFT128 (Hermitian packed) ----------------
#define NT1 512
__global__ __launch_bounds__(NT1) void p1(const float* __restrict__ images) {
    __shared__ float2 z[128 * 33];
    __shared__ float2 tw[64];
    const int b = blockIdx.y, X0 = blockIdx.x * 32;
    for (int i = threadIdx.x; i < 64; i += NT1) tw[i] = g_TW[i];
    for (int idx = threadIdx.x; idx < 4096; idx += NT1) {
        int l = idx >> 7, y = idx & 127;
        float I = images[(b * 128 + X0 + l) * 128 + y];
        float sv, cv;
        sincosf(0.5f * (float)PI_D * I, &sv, &cv);
        z[y * 33 + l] = make_float2(cv * (1.0f / 128.0f), sv * (1.0f / 128.0f));
    }
    __syncthreads();
    fft_run<false, NT1, 33, 1, 5, 0, 0, 7>(z, tw, 1.f);
    for (int idx = threadIdx.x; idx < 4096; idx += NT1) {
        int l = idx >> 7, kb = idx & 127;
        float2 Z = z[kb * 33 + l];
        float2 Zn = z[g_NR[kb] * 33 + l];
        float2 C  = make_float2(0.5f * (Z.x + Zn.x), 0.5f * (Z.y - Zn.y));
        float2 Sf = make_float2(0.5f * (Z.y + Zn.y), 0.5f * (Zn.x - Z.x));
        int X = X0 + l;
        g_S[((b * 2 + 0) * 128 + X) * 128 + kb] = C;
        g_S[((b * 2 + 1) * 128 + X) * 128 + kb] = Sf;
    }
}

// ---------------- P2: x-FFT128 + mux0 + x-IFFT128 + x-FFT64(halves) ----------------
#define NT2 512
__global__ __launch_bounds__(NT2) void p2() {
    __shared__ float2 tile[2 * 128 * 16];
    __shared__ float2 tw[64];
    const int b = blockIdx.y, y0 = blockIdx.x * 16;
    for (int i = threadIdx.x; i < 64; i += NT2) tw[i] = g_TW[i];
    for (int idx = threadIdx.x; idx < 4096; idx += NT2) {
        int yl = idx & 15, X = (idx >> 4) & 127, f = idx >> 11;
        tile[f * 2048 + X * 16 + yl] = g_S[((b * 2 + f) * 128 + X) * 128 + y0 + yl];
    }
    __syncthreads();
    fft_run<false, NT2, 16, 1, 4, 2048, 1, 7>(tile, tw, 1.f);
    for (int idx = threadIdx.x; idx < 2048; idx += NT2) {
        int yl = idx & 15, kxb = idx >> 4;
        int off = kxb * 16 + yl;
        float2 q0 = tile[off], q1 = tile[2048 + off];
        int ui = ((kxb << 7) + y0 + yl) * 2;
        apply_mux(q0, q1, g_U0[ui], g_U0[ui + 1]);
        tile[off] = q0; tile[2048 + off] = q1;
    }
    __syncthreads();
    fft_run<true,  NT2, 16, 1, 4, 2048, 1, 7>(tile, tw, 1.0f / 128.0f);
    fft_run<false, NT2, 16, 1, 4, 1024, 2, 6>(tile, tw, 1.f);   // halves x planes
    for (int idx = threadIdx.x; idx < 4096; idx += NT2) {
        int yl = idx & 15, X = (idx >> 4) & 127, f = idx >> 11;
        g_S[((b * 2 + f) * 128 + X) * 128 + y0 + yl] = tile[f * 2048 + X * 16 + yl];
    }
}

// ---------------- P35: y-junction + mux1 + x-junction + y-junction + mux2
//                   + final IFFT32s + measure + partial GEMV ----------------
#define NT3 512
#define P35_SMEM (132096 + 512 + 8192 + 640)
__global__ __launch_bounds__(NT3, 1) void p35(const float* __restrict__ W) {
    extern __shared__ char sm[];
    float2* tile = (float2*)sm;                            // [2][64][129]
    float2* tw   = (float2*)(sm + 132096);
    float*  prob = (float*)(sm + 132096 + 512);            // 2048 f32
    float*  red  = (float*)(sm + 132096 + 512 + 8192);     // 16*10 f32
    const int b = blockIdx.y, xc1 = blockIdx.x;
    for (int i = threadIdx.x; i < 64; i += NT3) tw[i] = g_TW[i];
    for (int idx = threadIdx.x; idx < 16384; idx += NT3) {
        int Y = idx & 127, X = (idx >> 7) & 63, f = idx >> 13;
        tile[f * 8256 + X * 129 + Y] = g_S[((b * 2 + f) * 128 + xc1 * 64 + X) * 128 + Y];
    }
    __syncthreads();
    // y junction 128->64
    fft_run8<true,  NT3, 1, 129, 7, 0,  0, 7>(tile, tw, 1.0f / 128.0f);
    fft_run8<false, NT3, 1, 129, 7, 64, 1, 6>(tile, tw, 1.f);
    // mux1
    for (int idx = threadIdx.x; idx < 8192; idx += NT3) {
        int Y = idx & 127, X = idx >> 7;
        int off = X * 129 + Y;
        float2 q0 = tile[off], q1 = tile[8256 + off];
        int yc1 = Y >> 6, Yb = Y & 63;
        int ui = (((xc1 * 2 + yc1) << 12) + (X << 6) + Yb) * 2;
        apply_mux(q0, q1, g_U1[ui], g_U1[ui + 1]);
        tile[off] = q0; tile[8256 + off] = q1;
    }
    __syncthreads();
    // x junction 64->32, then y junction 64->32
    fft_run8<true,  NT3, 129, 1, 7, 8256, 1, 6>(tile, tw, 1.0f / 64.0f);
    fft_run8<false, NT3, 129, 1, 7, 4128, 2, 5>(tile, tw, 1.f);
    fft_run8<true,  NT3, 1, 129, 7, 64, 1, 6>(tile, tw, 1.0f / 64.0f);
    fft_run8<false, NT3, 1, 129, 7, 32, 2, 5>(tile, tw, 1.f);
    // mux2
    for (int idx = threadIdx.x; idx < 8192; idx += NT3) {
        int Y = idx & 127, X = idx >> 7;
        int off = X * 129 + Y;
        float2 q0 = tile[off], q1 = tile[8256 + off];
        int xc2 = X >> 5, yc2 = (Y >> 5) & 1;
        int ui = (((xc2 * 2 + yc2) << 10) + ((X & 31) << 5) + (Y & 31)) * 2;
        apply_mux(q0, q1, g_U2[ui], g_U2[ui + 1]);
        tile[off] = q0; tile[8256 + off] = q1;
    }
    __syncthreads();
    // final iqft2d (32-point both axes)
    fft_run8<true, NT3, 129, 1, 7, 4128, 2, 5>(tile, tw, 1.0f / 32.0f);
    fft_run8<true, NT3, 1, 129, 7, 32,   2, 5>(tile, tw, 1.0f / 32.0f);
    // measurement: partial prob over (xc2, yc1, yc2)
    for (int idx = threadIdx.x; idx < 2048; idx += NT3) {
        int f = idx & 1, ya = (idx >> 1) & 31, xa = idx >> 6;
        float s = 0.f;
        #pragma unroll
        for (int xc2 = 0; xc2 < 2; ++xc2)
            #pragma unroll
            for (int yq = 0; yq < 4; ++yq) {
                float2 v = tile[f * 8256 + (xc2 * 32 + xa) * 129 + yq * 32 + ya];
                s += v.x * v.x + v.y * v.y;
            }
        prob[idx] = s;
    }
    __syncthreads();
    // partial GEMV: thread covers 4 features
    float acc[10];
    #pragma unroll
    for (int c = 0; c < 10; ++c) acc[c] = 0.f;
    {
        int j0 = threadIdx.x * 4;
        float4 pv = *(const float4*)(prob + j0);
        #pragma unroll
        for (int c = 0; c < 10; ++c) {
            float4 wv = *(const float4*)(W + c * 2048 + j0);
            acc[c] = fmaf(pv.x, wv.x, fmaf(pv.y, wv.y, fmaf(pv.z, wv.z, fmaf(pv.w, wv.w, acc[c]))));
        }
    }
    #pragma unroll
    for (int c = 0; c < 10; ++c)
        #pragma unroll
        for (int o = 16; o > 0; o >>= 1)
            acc[c] += __shfl_down_sync(0xffffffffu, acc[c], o);
    const int warp = threadIdx.x >> 5, lane = threadIdx.x & 31;
    if (lane == 0)
        #pragma unroll
        for (int c = 0; c < 10; ++c) red[warp * 10 + c] = acc[c];
    __syncthreads();
    if (threadIdx.x < 10) {
        float s = 0.f;
        #pragma unroll
        for (int w = 0; w < 16; ++w) s += red[w * 10 + threadIdx.x];
        g_part[(b * 2 + xc1) * 10 + threadIdx.x] = s;
    }
}

// ---------------- combine ----------------
__global__ void pc(const float* __restrict__ bias, float* __restrict__ out) {
    int i = blockIdx.x * blockDim.x + threadIdx.x;
    if (i < 5120) {
        int b = i / 10, c = i % 10;
        out[i] = bias[c] + g_part[(b * 2) * 10 + c] + g_part[(b * 2 + 1) * 10 + c];
    }
}

// ---------------- launch ----------------
extern "C" void kernel_launch(void* const* d_in, const int* in_sizes, int n_in,
                              void* d_out, int out_size) {
    const float* images = (const float*)d_in[0];
    const float* mux0 = (const float*)d_in[1];
    const float* mux1 = (const float*)d_in[2];
    const float* mux2 = (const float*)d_in[3];
    const float* W = (const float*)d_in[4];
    const float* bias = (const float*)d_in[5];
    float* out = (float*)d_out;
    (void)in_sizes; (void)n_in; (void)out_size;

    cudaFuncSetAttribute(p35, cudaFuncAttributeMaxDynamicSharedMemorySize, P35_SMEM);

    k0<<<64, 256>>>(mux0, mux1, mux2);
    p1<<<dim3(4, 512), NT1>>>(images);
    p2<<<dim3(8, 512), NT2>>>();
    p35<<<dim3(2, 512), NT3, P35_SMEM>>>(W);
    pc<<<10, 512>>>(bias, out);
}

// round 7
// speedup vs baseline: 1.5442x; 1.5442x over previous
#include <cuda_runtime.h>
#include <math.h>

#define PI_D 3.14159265358979323846

// ---------------- static device scratch ----------------
__device__ float4 g_S4[512 * 128 * 128];      // state [b][X][Y], float4 = (f0, f1) complex pair
__device__ float4 g_U0[128 * 128 * 2];        // mux0 unitaries, bitrev-permuted
__device__ float4 g_U1[2 * 2 * 64 * 64 * 2];
__device__ float4 g_U2[2 * 2 * 32 * 32 * 2];
__device__ float2 g_TW[64];                   // exp(-2*pi*i*t/128)
__device__ int    g_NR[128];                  // bitrev-domain negation table
__device__ float  g_part[512 * 2 * 10];       // partial logits per (b, xc1)

// ---- float2 complex helpers ----
__device__ __forceinline__ float2 cmul(float2 a, float2 b) {
    return make_float2(a.x * b.x - a.y * b.y, a.x * b.y + a.y * b.x);
}
__device__ __forceinline__ float2 cmulc(float2 a, float2 b) {
    return make_float2(a.x * b.x + a.y * b.y, a.y * b.x - a.x * b.y);
}
__device__ __forceinline__ float2 f2add(float2 a, float2 b) { return make_float2(a.x + b.x, a.y + b.y); }
__device__ __forceinline__ float2 f2sub(float2 a, float2 b) { return make_float2(a.x - b.x, a.y - b.y); }
__device__ __forceinline__ float2 csq(float2 a) { return make_float2(a.x * a.x - a.y * a.y, 2.f * a.x * a.y); }

// ---- float4 = two complex numbers, same twiddle applied to both ----
__device__ __forceinline__ float4 f4add(float4 a, float4 b) {
    return make_float4(a.x + b.x, a.y + b.y, a.z + b.z, a.w + b.w);
}
__device__ __forceinline__ float4 f4sub(float4 a, float4 b) {
    return make_float4(a.x - b.x, a.y - b.y, a.z - b.z, a.w - b.w);
}
__device__ __forceinline__ float4 f4sc(float4 a, float s) {
    return make_float4(a.x * s, a.y * s, a.z * s, a.w * s);
}
__device__ __forceinline__ float4 c4mul(float4 v, float2 w) {
    return make_float4(v.x * w.x - v.y * w.y, v.x * w.y + v.y * w.x,
                       v.z * w.x - v.w * w.y, v.z * w.y + v.w * w.x);
}
__device__ __forceinline__ float4 c4mulc(float4 v, float2 w) {
    return make_float4(v.x * w.x + v.y * w.y, v.y * w.x - v.x * w.y,
                       v.z * w.x + v.w * w.y, v.w * w.x - v.z * w.y);
}
// mux on one float4 site: q0=(x,y), q1=(z,w)
__device__ __forceinline__ float4 mux4(float4 v, float4 uA, float4 uB) {
    float4 o;
    o.x = uA.x * v.x - uA.y * v.y + uA.z * v.z - uA.w * v.w;
    o.y = uA.x * v.y + uA.y * v.x + uA.z * v.w + uA.w * v.z;
    o.z = uB.x * v.x - uB.y * v.y + uB.z * v.z - uB.w * v.w;
    o.w = uB.x * v.y + uB.y * v.x + uB.z * v.w + uB.w * v.z;
    return o;
}

// =====================================================================
// float4 FFT passes. element (line, p) at base[(line&(2^LG1-1))*SL1 + (line>>LG1)*SL2 + p*SP]
// FWD: DIF natural->bitrev; INV: DIT bitrev->natural (conj twiddles), scale on LAST.
// =====================================================================
template<bool INV, int NTT, int SP, int SL1, int LG1, int SL2, int LG2, int LOGN, int S, bool LAST>
__device__ __forceinline__ void pass4(float4* __restrict__ base,
                                      const float2* __restrict__ tw, float scale) {
    constexpr int L = 1 << (LG1 + LG2);
    constexpr int ITEMS = L << (LOGN - 2);
    constexpr int h = 1 << S;
    for (int u = threadIdx.x; u < ITEMS; u += NTT) {
        const int line = u & (L - 1);
        const int loff = (line & ((1 << LG1) - 1)) * SL1 + (line >> LG1) * SL2;
        const int v = u >> (LG1 + LG2);
        const int t = v & (h - 1);
        const int p = ((v >> S) << (S + 2)) + t;
        float4* e = base + loff + p * SP;
        float4 a = e[0], b = e[h * SP], c = e[2 * h * SP], d = e[3 * h * SP];
        const float2 w0 = tw[t << (5 - S)];
        const float2 w1 = make_float2(w0.y, -w0.x);
        const float2 w2 = csq(w0);
        if constexpr (!INV) {
            float4 ac = f4add(a, c), bd = f4add(b, d);
            float4 cP = c4mul(f4sub(a, c), w0);
            float4 dP = c4mul(f4sub(b, d), w1);
            e[0]          = f4add(ac, bd);
            e[h * SP]     = c4mul(f4sub(ac, bd), w2);
            e[2 * h * SP] = f4add(cP, dP);
            e[3 * h * SP] = c4mul(f4sub(cP, dP), w2);
        } else {
            float4 bw = c4mulc(b, w2), dw = c4mulc(d, w2);
            float4 aP = f4add(a, bw), bP = f4sub(a, bw);
            float4 cP = f4add(c, dw), dP = f4sub(c, dw);
            float4 cw = c4mulc(cP, w0), dq = c4mulc(dP, w1);
            float4 o0 = f4add(aP, cw), o2 = f4sub(aP, cw);
            float4 o1 = f4add(bP, dq), o3 = f4sub(bP, dq);
            if constexpr (LAST) {
                o0 = f4sc(o0, scale); o1 = f4sc(o1, scale);
                o2 = f4sc(o2, scale); o3 = f4sc(o3, scale);
            }
            e[0] = o0; e[h * SP] = o1; e[2 * h * SP] = o2; e[3 * h * SP] = o3;
        }
    }
    __syncthreads();
}

template<bool INV, int NTT, int SP, int SL1, int LG1, int SL2, int LG2, int LOGN, int S, bool LAST>
__device__ __forceinline__ void pass2(float4* __restrict__ base,
                                      const float2* __restrict__ tw, float scale) {
    constexpr int L = 1 << (LG1 + LG2);
    constexpr int ITEMS = L << (LOGN - 1);
    constexpr int h = 1 << S;
    for (int u = threadIdx.x; u < ITEMS; u += NTT) {
        const int line = u & (L - 1);
        const int loff = (line & ((1 << LG1) - 1)) * SL1 + (line >> LG1) * SL2;
        const int v = u >> (LG1 + LG2);
        const int t = v & (h - 1);
        const int p = ((v >> S) << (S + 1)) + t;
        float4* e = base + loff + p * SP;
        float4 a = e[0], b = e[h * SP];
        const float2 w = tw[t << (6 - S)];
        if constexpr (!INV) {
            e[0]      = f4add(a, b);
            e[h * SP] = c4mul(f4sub(a, b), w);
        } else {
            float4 bw = c4mulc(b, w);
            float4 o0 = f4add(a, bw), o1 = f4sub(a, bw);
            if constexpr (LAST) { o0 = f4sc(o0, scale); o1 = f4sc(o1, scale); }
            e[0] = o0; e[h * SP] = o1;
        }
    }
    __syncthreads();
}

template<bool INV, int NTT, int SP, int SL1, int LG1, int SL2, int LG2, int LOGN>
__device__ __forceinline__ void fft_run(float4* __restrict__ base,
                                        const float2* __restrict__ tw, float scale) {
    if constexpr (!INV) {
        if constexpr (LOGN == 7) {
            pass4<false, NTT, SP, SL1, LG1, SL2, LG2, 7, 5, false>(base, tw, 1.f);
            pass4<false, NTT, SP, SL1, LG1, SL2, LG2, 7, 3, false>(base, tw, 1.f);
            pass4<false, NTT, SP, SL1, LG1, SL2, LG2, 7, 1, false>(base, tw, 1.f);
            pass2<false, NTT, SP, SL1, LG1, SL2, LG2, 7, 0, false>(base, tw, 1.f);
        } else if constexpr (LOGN == 6) {
            pass4<false, NTT, SP, SL1, LG1, SL2, LG2, 6, 4, false>(base, tw, 1.f);
            pass4<false, NTT, SP, SL1, LG1, SL2, LG2, 6, 2, false>(base, tw, 1.f);
            pass4<false, NTT, SP, SL1, LG1, SL2, LG2, 6, 0, false>(base, tw, 1.f);
        } else {
            pass4<false, NTT, SP, SL1, LG1, SL2, LG2, 5, 3, false>(base, tw, 1.f);
            pass4<false, NTT, SP, SL1, LG1, SL2, LG2, 5, 1, false>(base, tw, 1.f);
            pass2<false, NTT, SP, SL1, LG1, SL2, LG2, 5, 0, false>(base, tw, 1.f);
        }
    } else {
        if constexpr (LOGN == 7) {
            pass4<true, NTT, SP, SL1, LG1, SL2, LG2, 7, 0, false>(base, tw, 1.f);
            pass4<true, NTT, SP, SL1, LG1, SL2, LG2, 7, 2, false>(base, tw, 1.f);
            pass4<true, NTT, SP, SL1, LG1, SL2, LG2, 7, 4, false>(base, tw, 1.f);
            pass2<true, NTT, SP, SL1, LG1, SL2, LG2, 7, 6, true >(base, tw, scale);
        } else if constexpr (LOGN == 6) {
            pass4<true, NTT, SP, SL1, LG1, SL2, LG2, 6, 0, false>(base, tw, 1.f);
            pass4<true, NTT, SP, SL1, LG1, SL2, LG2, 6, 2, false>(base, tw, 1.f);
            pass4<true, NTT, SP, SL1, LG1, SL2, LG2, 6, 4, true >(base, tw, scale);
        } else {
            pass4<true, NTT, SP, SL1, LG1, SL2, LG2, 5, 0, false>(base, tw, 1.f);
            pass4<true, NTT, SP, SL1, LG1, SL2, LG2, 5, 2, false>(base, tw, 1.f);
            pass2<true, NTT, SP, SL1, LG1, SL2, LG2, 5, 4, true >(base, tw, scale);
        }
    }
}

// ---------------- float2 passes (p1 only: packed Hermitian plane) ----------------
template<bool INV, int NTT, int SP, int LG1, int LOGN, int S, bool LAST>
__device__ __forceinline__ void pass4s(float2* __restrict__ base,
                                       const float2* __restrict__ tw, float scale) {
    constexpr int L = 1 << LG1;
    constexpr int ITEMS = L << (LOGN - 2);
    constexpr int h = 1 << S;
    for (int u = threadIdx.x; u < ITEMS; u += NTT) {
        const int loff = (u & (L - 1));
        const int v = u >> LG1;
        const int t = v & (h - 1);
        const int p = ((v >> S) << (S + 2)) + t;
        float2* e = base + loff + p * SP;
        float2 a = e[0], b = e[h * SP], c = e[2 * h * SP], d = e[3 * h * SP];
        const float2 w0 = tw[t << (5 - S)];
        const float2 w1 = make_float2(w0.y, -w0.x);
        const float2 w2 = csq(w0);
        if constexpr (!INV) {
            float2 ac = f2add(a, c), bd = f2add(b, d);
            float2 cP = cmul(f2sub(a, c), w0);
            float2 dP = cmul(f2sub(b, d), w1);
            e[0]          = f2add(ac, bd);
            e[h * SP]     = cmul(f2sub(ac, bd), w2);
            e[2 * h * SP] = f2add(cP, dP);
            e[3 * h * SP] = cmul(f2sub(cP, dP), w2);
        }
    }
    __syncthreads();
}
template<bool INV, int NTT, int SP, int LG1, int LOGN, int S, bool LAST>
__device__ __forceinline__ void pass2s(float2* __restrict__ base,
                                       const float2* __restrict__ tw, float scale) {
    constexpr int L = 1 << LG1;
    constexpr int ITEMS = L << (LOGN - 1);
    constexpr int h = 1 << S;
    for (int u = threadIdx.x; u < ITEMS; u += NTT) {
        const int loff = (u & (L - 1));
        const int v = u >> LG1;
        const int t = v & (h - 1);
        const int p = ((v >> S) << (S + 1)) + t;
        float2* e = base + loff + p * SP;
        float2 a = e[0], b = e[h * SP];
        const float2 w = tw[t << (6 - S)];
        if constexpr (!INV) {
            e[0]      = f2add(a, b);
            e[h * SP] = cmul(f2sub(a, b), w);
        }
    }
    __syncthreads();
}

// ---------------- K0: precompute ----------------
__device__ __forceinline__ void writeU(float4* dst, float axf, float ayf, float azf) {
    double ax = axf, ay = ayf, az = azf;
    double r = sqrt(ax * ax + ay * ay + az * az + 1e-20);
    double cr = cos(r), sn = sin(r) / r;
    dst[0] = make_float4((float)cr, (float)(-az * sn), (float)(-ay * sn), (float)(-ax * sn));
    dst[1] = make_float4((float)(ay * sn), (float)(-ax * sn), (float)cr, (float)(az * sn));
}

__global__ void k0(const float* __restrict__ mux0, const float* __restrict__ mux1,
                   const float* __restrict__ mux2) {
    int idx = blockIdx.x * blockDim.x + threadIdx.x;   // 16384 threads
    if (idx < 64) {
        double ang = -2.0 * PI_D * (double)idx / 128.0;
        g_TW[idx] = make_float2((float)cos(ang), (float)sin(ang));
    }
    if (idx < 128) {
        int k = __brev((unsigned)idx) >> 25;
        g_NR[idx] = (int)(__brev((unsigned)((128 - k) & 127)) >> 25);
    }
    {
        int kxb = idx >> 7, kyb = idx & 127;
        int kx = __brev((unsigned)kxb) >> 25, ky = __brev((unsigned)kyb) >> 25;
        const float* c = mux0 + (kx * 128 + ky) * 3;
        writeU(&g_U0[idx * 2], c[0], c[1], c[2]);
    }
    {
        int cx = idx >> 13, cy = (idx >> 12) & 1, kxb = (idx >> 6) & 63, kyb = idx & 63;
        int kx = __brev((unsigned)kxb) >> 26, ky = __brev((unsigned)kyb) >> 26;
        const float* c = mux1 + (((cx * 2 + cy) * 64 + kx) * 64 + ky) * 3;
        writeU(&g_U1[idx * 2], c[0], c[1], c[2]);
    }
    if (idx < 4096) {
        int cx = idx >> 11, cy = (idx >> 10) & 1, kxb = (idx >> 5) & 31, kyb = idx & 31;
        int kx = __brev((unsigned)kxb) >> 27, ky = __brev((unsigned)kyb) >> 27;
        const float* c = mux2 + (((cx * 2 + cy) * 32 + kx) * 32 + ky) * 3;
        writeU(&g_U2[idx * 2], c[0], c[1], c[2]);
    }
}

// ---------------- P1: encode + y-FFT128 (Hermitian packed) ----------------
#define NT1 512
__global__ __launch_bounds__(NT1) void p1(const float* __restrict__ images) {
    __shared__ float2 z[128 * 33];
    __shared__ float2 tw[64];
    const int b = blockIdx.y, X0 = blockIdx.x * 32;
    for (int i = threadIdx.x; i < 64; i += NT1) tw[i] = g_TW[i];
    for (int idx = threadIdx.x; idx < 4096; idx += NT1) {
        int l = idx >> 7, y = idx & 127;
        float I = images[(b * 128 + X0 + l) * 128 + y];
        float sv, cv;
        sincosf(0.5f * (float)PI_D * I, &sv, &cv);
        z[y * 33 + l] = make_float2(cv * (1.0f / 128.0f), sv * (1.0f / 128.0f));
    }
    __syncthreads();
    // fwd 128-point FFT over y (positions stride 33, 32 lines stride 1)
    pass4s<false, NT1, 33, 5, 7, 5, false>(z, tw, 1.f);
    pass4s<false, NT1, 33, 5, 7, 3, false>(z, tw, 1.f);
    pass4s<false, NT1, 33, 5, 7, 1, false>(z, tw, 1.f);
    pass2s<false, NT1, 33, 5, 7, 0, false>(z, tw, 1.f);
    for (int idx = threadIdx.x; idx < 4096; idx += NT1) {
        int l = idx >> 7, kb = idx & 127;
        float2 Z = z[kb * 33 + l];
        float2 Zn = z[g_NR[kb] * 33 + l];
        float2 C  = make_float2(0.5f * (Z.x + Zn.x), 0.5f * (Z.y - Zn.y));
        float2 Sf = make_float2(0.5f * (Z.y + Zn.y), 0.5f * (Zn.x - Z.x));
        int X = X0 + l;
        g_S4[(b * 128 + X) * 128 + kb] = make_float4(C.x, C.y, Sf.x, Sf.y);
    }
}

// ---------------- P2: x-FFT128 + mux0 + x-IFFT128 + x-FFT64(halves) ----------------
#define NT2 512
__global__ __launch_bounds__(NT2) void p2() {
    __shared__ float4 tile[128 * 16];
    __shared__ float2 tw[64];
    const int b = blockIdx.y, y0 = blockIdx.x * 16;
    for (int i = threadIdx.x; i < 64; i += NT2) tw[i] = g_TW[i];
    for (int idx = threadIdx.x; idx < 2048; idx += NT2) {
        int yl = idx & 15, X = idx >> 4;
        tile[X * 16 + yl] = g_S4[(b * 128 + X) * 128 + y0 + yl];
    }
    __syncthreads();
    fft_run<false, NT2, 16, 1, 4, 0, 0, 7>(tile, tw, 1.f);
    for (int idx = threadIdx.x; idx < 2048; idx += NT2) {
        int yl = idx & 15, kxb = idx >> 4;
        int ui = ((kxb << 7) + y0 + yl) * 2;
        tile[kxb * 16 + yl] = mux4(tile[kxb * 16 + yl], g_U0[ui], g_U0[ui + 1]);
    }
    __syncthreads();
    fft_run<true,  NT2, 16, 1, 4, 0,    0, 7>(tile, tw, 1.0f / 128.0f);
    fft_run<false, NT2, 16, 1, 4, 1024, 1, 6>(tile, tw, 1.f);   // x halves
    for (int idx = threadIdx.x; idx < 2048; idx += NT2) {
        int yl = idx & 15, X = idx >> 4;
        g_S4[(b * 128 + X) * 128 + y0 + yl] = tile[X * 16 + yl];
    }
}

// ---------------- P35: y-junction + mux1 + x-junction + y-junction + mux2
//                   + final IFFT32s + measure + partial GEMV ----------------
#define NT3 1024
#define P35_SMEM (132096 + 512 + 8192 + 1280)
__global__ __launch_bounds__(NT3) void p35(const float* __restrict__ W) {
    extern __shared__ char sm[];
    float4* tile = (float4*)sm;                            // [64 X][129] float4
    float2* tw   = (float2*)(sm + 132096);
    float*  prob = (float*)(sm + 132096 + 512);            // 2048 f32
    float*  red  = (float*)(sm + 132096 + 512 + 8192);     // 32*10 f32
    const int b = blockIdx.y, xc1 = blockIdx.x;
    for (int i = threadIdx.x; i < 64; i += NT3) tw[i] = g_TW[i];
    for (int idx = threadIdx.x; idx < 8192; idx += NT3) {
        int Y = idx & 127, X = idx >> 7;
        tile[X * 129 + Y] = g_S4[(b * 128 + xc1 * 64 + X) * 128 + Y];
    }
    __syncthreads();
    // y junction 128->64
    fft_run<true,  NT3, 1, 129, 6, 0,  0, 7>(tile, tw, 1.0f / 128.0f);
    fft_run<false, NT3, 1, 129, 6, 64, 1, 6>(tile, tw, 1.f);
    // mux1
    for (int idx = threadIdx.x; idx < 8192; idx += NT3) {
        int Y = idx & 127, X = idx >> 7;
        int yc1 = Y >> 6, Yb = Y & 63;
        int ui = (((xc1 * 2 + yc1) << 12) + (X << 6) + Yb) * 2;
        tile[X * 129 + Y] = mux4(tile[X * 129 + Y], g_U1[ui], g_U1[ui + 1]);
    }
    __syncthreads();
    // x junction 64->32, then y junction 64->32
    fft_run<true,  NT3, 129, 1, 7, 0,    0, 6>(tile, tw, 1.0f / 64.0f);
    fft_run<false, NT3, 129, 1, 7, 4128, 1, 5>(tile, tw, 1.f);
    fft_run<true,  NT3, 1, 129, 6, 64, 1, 6>(tile, tw, 1.0f / 64.0f);
    fft_run<false, NT3, 1, 129, 6, 32, 2, 5>(tile, tw, 1.f);
    // mux2
    for (int idx = threadIdx.x; idx < 8192; idx += NT3) {
        int Y = idx & 127, X = idx >> 7;
        int xc2 = X >> 5, yc2 = (Y >> 5) & 1;
        int ui = (((xc2 * 2 + yc2) << 10) + ((X & 31) << 5) + (Y & 31)) * 2;
        tile[X * 129 + Y] = mux4(tile[X * 129 + Y], g_U2[ui], g_U2[ui + 1]);
    }
    __syncthreads();
    // final iqft2d (32-point both axes)
    fft_run<true, NT3, 129, 1, 7, 4128, 1, 5>(tile, tw, 1.0f / 32.0f);
    fft_run<true, NT3, 1, 129, 6, 32,   2, 5>(tile, tw, 1.0f / 32.0f);
    // measurement: partial prob over (xc2, yc1, yc2)
    for (int idx = threadIdx.x; idx < 1024; idx += NT3) {
        int ya = idx & 31, xa = idx >> 5;
        float s0 = 0.f, s1 = 0.f;
        #pragma unroll
        for (int xc2 = 0; xc2 < 2; ++xc2)
            #pragma unroll
            for (int yq = 0; yq < 4; ++yq) {
                float4 v = tile[(xc2 * 32 + xa) * 129 + yq * 32 + ya];
                s0 += v.x * v.x + v.y * v.y;
                s1 += v.z * v.z + v.w * v.w;
            }
        prob[(xa * 32 + ya) * 2 + 0] = s0;
        prob[(xa * 32 + ya) * 2 + 1] = s1;
    }
    __syncthreads();
    // partial GEMV
    float acc[10];
    #pragma unroll
    for (int c = 0; c < 10; ++c) acc[c] = 0.f;
    {
        int j0 = threadIdx.x * 2;
        float2 pv = *(const float2*)(prob + j0);
        #pragma unroll
        for (int c = 0; c < 10; ++c) {
            float2 wv = *(const float2*)(W + c * 2048 + j0);
            acc[c] = fmaf(pv.x, wv.x, fmaf(pv.y, wv.y, acc[c]));
        }
    }
    #pragma unroll
    for (int c = 0; c < 10; ++c)
        #pragma unroll
        for (int o = 16; o > 0; o >>= 1)
            acc[c] += __shfl_down_sync(0xffffffffu, acc[c], o);
    const int warp = threadIdx.x >> 5, lane = threadIdx.x & 31;
    if (lane == 0)
        #pragma unroll
        for (int c = 0; c < 10; ++c) red[warp * 10 + c] = acc[c];
    __syncthreads();
    if (threadIdx.x < 10) {
        float s = 0.f;
        #pragma unroll
        for (int w = 0; w < 32; ++w) s += red[w * 10 + threadIdx.x];
        g_part[(b * 2 + xc1) * 10 + threadIdx.x] = s;
    }
}

// ---------------- combine ----------------
__global__ void pc(const float* __restrict__ bias, float* __restrict__ out) {
    int i = blockIdx.x * blockDim.x + threadIdx.x;
    if (i < 5120) {
        int b = i / 10, c = i % 10;
        out[i] = bias[c] + g_part[(b * 2) * 10 + c] + g_part[(b * 2 + 1) * 10 + c];
    }
}

// ---------------- launch ----------------
extern "C" void kernel_launch(void* const* d_in, const int* in_sizes, int n_in,
                              void* d_out, int out_size) {
    const float* images = (const float*)d_in[0];
    const float* mux0 = (const float*)d_in[1];
    const float* mux1 = (const float*)d_in[2];
    const float* mux2 = (const float*)d_in[3];
    const float* W = (const float*)d_in[4];
    const float* bias = (const float*)d_in[5];
    float* out = (float*)d_out;
    (void)in_sizes; (void)n_in; (void)out_size;

    cudaFuncSetAttribute(p35, cudaFuncAttributeMaxDynamicSharedMemorySize, P35_SMEM);

    k0<<<64, 256>>>(mux0, mux1, mux2);
    p1<<<dim3(4, 512), NT1>>>(images);
    p2<<<dim3(8, 512), NT2>>>();
    p35<<<dim3(2, 512), NT3, P35_SMEM>>>(W);
    pc<<<10, 512>>>(bias, out);
}